// round 11
// baseline (speedup 1.0000x reference)
#include <cuda_runtime.h>

#define BATCH    32
#define D_IN     1024
#define D_OUT    1024
#define E_DIM    3076                 // D_OUT + 2*D_IN + 4
#define NRB      148                  // row blocks
#define ROWS_MAX 21
#define KQ_TOTAL 2052u                // rows with e >= D_OUT
#define SMEM_FLOATS (2 * ROWS_MAX * 1024 + 3 * 1024)
#define SMEM_BYTES  (SMEM_FLOATS * 4) // 184320

// Scratch + sync (allocation-free rule: __device__ globals)
__device__ float    g_out [BATCH * E_DIM];
__device__ float    g_kphi[BATCH * D_IN];
__device__ float    g_qphi[BATCH * D_IN];
__device__ float    g_sig [BATCH * 4];
__device__ unsigned g_cnt [BATCH];
__device__ unsigned g_flag[BATCH];

__global__ void srwm_init()
{
    for (int i = 0; i < BATCH; i++) { g_cnt[i] = 0; g_flag[i] = 0; }
}

// ---------------------------------------------------------------------------
// One-warp softmax over 1024 values (server block).
// ---------------------------------------------------------------------------
__device__ __forceinline__ void softmax1024(const float* __restrict__ src,
                                            float* __restrict__ dst, int lane)
{
    float4 v[8];
    float m = -1e30f;
#pragma unroll
    for (int j = 0; j < 8; j++) {
        v[j] = __ldcg(((const float4*)src) + lane + j * 32);
        m = fmaxf(m, fmaxf(fmaxf(v[j].x, v[j].y), fmaxf(v[j].z, v[j].w)));
    }
#pragma unroll
    for (int o = 16; o; o >>= 1) m = fmaxf(m, __shfl_xor_sync(0xffffffffu, m, o));
    float s = 0.f;
#pragma unroll
    for (int j = 0; j < 8; j++) {
        v[j].x = __expf(v[j].x - m); v[j].y = __expf(v[j].y - m);
        v[j].z = __expf(v[j].z - m); v[j].w = __expf(v[j].w - m);
        s += v[j].x + v[j].y + v[j].z + v[j].w;
    }
#pragma unroll
    for (int o = 16; o; o >>= 1) s += __shfl_xor_sync(0xffffffffu, s, o);
    const float inv = 1.0f / s;
#pragma unroll
    for (int j = 0; j < 8; j++) {
        float4 o4 = { v[j].x * inv, v[j].y * inv, v[j].z * inv, v[j].w * inv };
        ((float4*)dst)[lane + j * 32] = o4;
    }
}

// ---------------------------------------------------------------------------
// Fused persistent kernel: 148 row blocks + 1 softmax server block.
// Row block bid owns rows e = bid + l*148, double-buffered in smem.
// ---------------------------------------------------------------------------
__global__ void __launch_bounds__(512, 1)
srwm_fused(const float* __restrict__ w, const float* __restrict__ x,
           float* __restrict__ y, float* __restrict__ wout, int write_y)
{
    extern __shared__ float smem[];
    float* bufs[2] = { smem, smem + ROWS_MAX * 1024 };
    float* kq_s = smem + 2 * ROWS_MAX * 1024;       // kphi[1024] | qphi[1024]
    float* x_s  = kq_s + 2048;                      // x[1024]
    __shared__ float ssig[4];

    const int tid  = threadIdx.x;
    const int wid  = tid >> 5;
    const int lane = tid & 31;
    const int bid  = blockIdx.x;

    // =================== softmax / sigmoid server ===================
    if (bid == NRB) {
        for (int b = 0; b < BATCH; b++) {
            if (tid == 0) {
                while (*(volatile unsigned*)&g_cnt[b] < KQ_TOTAL) __nanosleep(64);
            }
            __syncthreads();
            __threadfence();
            if (wid == 0) {
                softmax1024(g_out + (size_t)b * E_DIM + D_OUT,
                            g_kphi + (size_t)b * D_IN, lane);
            } else if (wid == 1) {
                softmax1024(g_out + (size_t)b * E_DIM + D_OUT + D_IN,
                            g_qphi + (size_t)b * D_IN, lane);
            } else if (wid == 2 && lane < 4) {
                float t = __ldcg(&g_out[(size_t)b * E_DIM + D_OUT + 2 * D_IN + lane]);
                g_sig[b * 4 + lane] = 1.0f / (1.0f + __expf(-t));
            }
            __threadfence();
            __syncthreads();
            if (tid == 0) atomicExch(&g_flag[b], 1u);
        }
        return;
    }

    // =================== row block ===================
    const int nrows = (E_DIM - bid + NRB - 1) / NRB;     // 21 or 20
    unsigned nkq = 0;
    for (int l = 0; l < nrows; l++)
        if (bid + l * NRB >= D_OUT) nkq++;

    // -- mv: copy w rows of batch b into buf, dot vs x_s, post outputs --
    auto mv_batch = [&](float* buf, int b) {
        const float4* xs = (const float4*)x_s;
        for (int l = wid; l < nrows; l += 16) {
            const int e = bid + l * NRB;
            const float4* wrow = (const float4*)(w + ((size_t)b * E_DIM + e) * D_IN);
            float4* brow = (float4*)(buf + l * 1024);
            float acc = 0.f;
#pragma unroll
            for (int j = 0; j < 8; j++) {
                float4 wv = __ldcs(wrow + lane + j * 32);
                float4 xv = xs[lane + j * 32];
                brow[lane + j * 32] = wv;
                acc += wv.x * xv.x + wv.y * xv.y + wv.z * xv.z + wv.w * xv.w;
            }
#pragma unroll
            for (int o = 16; o; o >>= 1) acc += __shfl_xor_sync(0xffffffffu, acc, o);
            if (lane == 0) {
                if (e >= D_OUT) g_out[(size_t)b * E_DIM + e] = acc;
                else if (write_y) y[(size_t)b * D_OUT + e] = acc;
            }
        }
    };

    // -- update: rows of batch b from buf; dots vs staged kphi/qphi --
    auto up_batch = [&](const float* buf, int b) {
        const float4* kp = (const float4*)kq_s;
        const float4* qp = (const float4*)(kq_s + 1024);
        for (int l = wid; l < nrows; l += 16) {
            const int e = bid + l * NRB;
            const float4* brow = (const float4*)(buf + l * 1024);
            float4* orow = (float4*)(wout + ((size_t)b * E_DIM + e) * D_IN);
            float4 wv[8];
            float ab = 0.f, av = 0.f;
#pragma unroll
            for (int j = 0; j < 8; j++) {
                wv[j] = brow[lane + j * 32];
                float4 kv = kp[lane + j * 32];
                float4 qv = qp[lane + j * 32];
                ab += wv[j].x * kv.x + wv[j].y * kv.y + wv[j].z * kv.z + wv[j].w * kv.w;
                av += wv[j].x * qv.x + wv[j].y * qv.y + wv[j].z * qv.z + wv[j].w * qv.w;
            }
#pragma unroll
            for (int o = 16; o; o >>= 1) {
                ab += __shfl_xor_sync(0xffffffffu, ab, o);
                av += __shfl_xor_sync(0xffffffffu, av, o);
            }
            const int seg = (e < D_OUT) ? 0 : (e < D_OUT + D_IN) ? 1 :
                            (e < D_OUT + 2 * D_IN) ? 2 : 3;
            const float coeff = ssig[seg] * (av - ab);
#pragma unroll
            for (int j = 0; j < 8; j++) {
                float4 kv = kp[lane + j * 32];
                float4 o4 = { wv[j].x + coeff * kv.x, wv[j].y + coeff * kv.y,
                              wv[j].z + coeff * kv.z, wv[j].w + coeff * kv.w };
                __stcs(orow + lane + j * 32, o4);
            }
        }
    };

    auto stage_x = [&](int b) {
        if (tid < 256)
            ((float4*)x_s)[tid] = __ldg(((const float4*)(x + (size_t)b * D_IN)) + tid);
    };
    auto stage_kq = [&](int b) {
        if (tid < 256)
            ((float4*)kq_s)[tid] = __ldcg(((const float4*)(g_kphi + (size_t)b * D_IN)) + tid);
        else
            ((float4*)(kq_s + 1024))[tid - 256] =
                __ldcg(((const float4*)(g_qphi + (size_t)b * D_IN)) + (tid - 256));
        if (tid < 4) ssig[tid] = __ldcg(&g_sig[b * 4 + tid]);
    };
    auto post_cnt = [&](int b) {
        __threadfence();
        __syncthreads();
        if (tid == 0) atomicAdd(&g_cnt[b], nkq);
    };
    auto wait_flag = [&](int b) {
        if (tid == 0) {
            while (*(volatile unsigned*)&g_flag[b] == 0u) __nanosleep(64);
        }
        __syncthreads();
        __threadfence();
    };

    // -------- prologue: batch 0 --------
    stage_x(0);
    __syncthreads();
    mv_batch(bufs[0], 0);
    post_cnt(0);

    int cur = 0;
#pragma unroll 1
    for (int b = 0; b < BATCH; b++) {
        // load next batch into the other buffer (softmax(b) overlaps this)
        if (b + 1 < BATCH) {
            __syncthreads();               // x_s / buffer WAR
            stage_x(b + 1);
            __syncthreads();
            mv_batch(bufs[cur ^ 1], b + 1);
            post_cnt(b + 1);
        }
        // update batch b from its smem buffer
        wait_flag(b);
        stage_kq(b);
        __syncthreads();
        up_batch(bufs[cur], b);
        cur ^= 1;
        __syncthreads();                   // buffer WAR before next mv
    }
}

// ---------------------------------------------------------------------------
// kernel_launch: init + one fused kernel (2 graph nodes).
// ---------------------------------------------------------------------------
extern "C" void kernel_launch(void* const* d_in, const int* in_sizes, int n_in,
                              void* d_out, int out_size)
{
    const float* x = (const float*)d_in[0];
    const float* w = (const float*)d_in[1];
    if (n_in >= 2 && in_sizes[0] != BATCH * D_IN) {
        x = (const float*)d_in[1];
        w = (const float*)d_in[0];
    }

    const size_t wout_elems = (size_t)BATCH * E_DIM * D_IN;
    float* out = (float*)d_out;

    float* y_ptr    = out;
    float* wout_ptr = out + ((size_t)out_size - wout_elems);
    const int write_y = ((size_t)out_size > wout_elems) ? 1 : 0;

    static int configured = 0;
    if (!configured) {
        cudaFuncSetAttribute(srwm_fused,
                             cudaFuncAttributeMaxDynamicSharedMemorySize,
                             SMEM_BYTES);
        configured = 1;
    }

    srwm_init<<<1, 1>>>();
    srwm_fused<<<NRB + 1, 512, SMEM_BYTES>>>(w, x, y_ptr, wout_ptr, write_y);
}

// round 14
// speedup vs baseline: 1.9574x; 1.9574x over previous
#include <cuda_runtime.h>

#define BATCH   32
#define D_IN    1024
#define D_OUT   1024
#define E_DIM   3076                 // D_OUT + 2*D_IN + 4
#define NROWBLK 147
#define GWN     (NROWBLK * 8)        // 1176 row-warps
#define KQ_TOTAL 2052u               // rows with e >= 1024

// Scratch + sync (allocation-free rule: __device__ globals)
__device__ float    g_out [BATCH * E_DIM];   // only e >= D_OUT used
__device__ float    g_kphi[BATCH * D_IN];
__device__ float    g_qphi[BATCH * D_IN];
__device__ float    g_sig [BATCH * 4];
__device__ unsigned g_cnt [BATCH];
__device__ unsigned g_flag[BATCH];

__global__ void srwm_init()
{
    for (int i = 0; i < BATCH; i++) { g_cnt[i] = 0; g_flag[i] = 0; }
}

// ---------------------------------------------------------------------------
// Load one w row into a float4[8] register buffer (8 back-to-back LDG.128).
// ---------------------------------------------------------------------------
__device__ __forceinline__ void load_row(const float* __restrict__ w,
                                         int b, int e, int lane,
                                         float4 (&r)[8])
{
    const float4* p = (const float4*)(w + ((size_t)b * E_DIM + e) * D_IN);
#pragma unroll
    for (int j = 0; j < 8; j++) r[j] = __ldcs(p + lane + j * 32);
}

// Dot the buffered row against x[b], reduce, post to g_out / y.
__device__ __forceinline__ void dot_post(const float* __restrict__ x,
                                         float* __restrict__ y, int write_y,
                                         int b, int e, int lane,
                                         const float4 (&r)[8])
{
    const float4* x4 = (const float4*)(x + (size_t)b * D_IN);
    float acc = 0.f;
#pragma unroll
    for (int j = 0; j < 8; j++) {
        float4 xv = __ldg(x4 + lane + j * 32);
        acc += r[j].x * xv.x + r[j].y * xv.y + r[j].z * xv.z + r[j].w * xv.w;
    }
#pragma unroll
    for (int o = 16; o; o >>= 1) acc += __shfl_xor_sync(0xffffffffu, acc, o);
    if (lane == 0) {
        if (e >= D_OUT) g_out[(size_t)b * E_DIM + e] = acc;
        else if (write_y) y[(size_t)b * D_OUT + e] = acc;
    }
}

// Update one row from its register buffer: dots vs kphi/qphi, then
// w_out = w + sig*(v-vbar)*kphi.
__device__ __forceinline__ void up_row(float* __restrict__ wout,
                                       int b, int e, int lane,
                                       const float4 (&r)[8])
{
    const float4* kp = (const float4*)(g_kphi + (size_t)b * D_IN);
    const float4* qp = (const float4*)(g_qphi + (size_t)b * D_IN);
    float ab = 0.f, av = 0.f;
#pragma unroll
    for (int j = 0; j < 8; j++) {
        float4 kv = __ldg(kp + lane + j * 32);
        float4 qv = __ldg(qp + lane + j * 32);
        ab += r[j].x * kv.x + r[j].y * kv.y + r[j].z * kv.z + r[j].w * kv.w;
        av += r[j].x * qv.x + r[j].y * qv.y + r[j].z * qv.z + r[j].w * qv.w;
    }
#pragma unroll
    for (int o = 16; o; o >>= 1) {
        ab += __shfl_xor_sync(0xffffffffu, ab, o);
        av += __shfl_xor_sync(0xffffffffu, av, o);
    }
    const int seg = (e < D_OUT) ? 0 : (e < D_OUT + D_IN) ? 1 :
                    (e < D_OUT + 2 * D_IN) ? 2 : 3;
    const float coeff = __ldg(&g_sig[b * 4 + seg]) * (av - ab);
    float4* orow = (float4*)(wout + ((size_t)b * E_DIM + e) * D_IN);
#pragma unroll
    for (int j = 0; j < 8; j++) {
        float4 kv = __ldg(kp + lane + j * 32);
        float4 o4 = { r[j].x + coeff * kv.x, r[j].y + coeff * kv.y,
                      r[j].z + coeff * kv.z, r[j].w + coeff * kv.w };
        __stcs(orow + lane + j * 32, o4);
    }
}

// ---------------------------------------------------------------------------
// One-warp softmax over 1024 values (server block).
// ---------------------------------------------------------------------------
__device__ __forceinline__ void softmax1024(const float* __restrict__ src,
                                            float* __restrict__ dst, int lane)
{
    float4 v[8];
    float m = -1e30f;
#pragma unroll
    for (int j = 0; j < 8; j++) {
        v[j] = __ldcg(((const float4*)src) + lane + j * 32);
        m = fmaxf(m, fmaxf(fmaxf(v[j].x, v[j].y), fmaxf(v[j].z, v[j].w)));
    }
#pragma unroll
    for (int o = 16; o; o >>= 1) m = fmaxf(m, __shfl_xor_sync(0xffffffffu, m, o));
    float s = 0.f;
#pragma unroll
    for (int j = 0; j < 8; j++) {
        v[j].x = __expf(v[j].x - m); v[j].y = __expf(v[j].y - m);
        v[j].z = __expf(v[j].z - m); v[j].w = __expf(v[j].w - m);
        s += v[j].x + v[j].y + v[j].z + v[j].w;
    }
#pragma unroll
    for (int o = 16; o; o >>= 1) s += __shfl_xor_sync(0xffffffffu, s, o);
    const float inv = 1.0f / s;
#pragma unroll
    for (int j = 0; j < 8; j++) {
        float4 o4 = { v[j].x * inv, v[j].y * inv, v[j].z * inv, v[j].w * inv };
        ((float4*)dst)[lane + j * 32] = o4;
    }
}

// ---------------------------------------------------------------------------
// Fused persistent kernel. Block NROWBLK = softmax/sigmoid server; blocks
// 0..146 are row blocks (8 warps, 3 rows each, double-buffered, warp-autonomous).
// ---------------------------------------------------------------------------
__global__ void __launch_bounds__(256, 1)
srwm_fused(const float* __restrict__ w, const float* __restrict__ x,
           float* __restrict__ y, float* __restrict__ wout, int write_y)
{
    const int tid  = threadIdx.x;
    const int wid  = tid >> 5;
    const int lane = tid & 31;
    const int bid  = blockIdx.x;

    if (bid == NROWBLK) {
        // ---------------- softmax / sigmoid server ----------------
        if (wid > 2) return;
        for (int b = 0; b < BATCH; b++) {
            while (*(volatile unsigned*)&g_cnt[b] < KQ_TOTAL) __nanosleep(64);
            __threadfence();
            if (wid == 0) {
                softmax1024(g_out + (size_t)b * E_DIM + D_OUT,
                            g_kphi + (size_t)b * D_IN, lane);
            } else if (wid == 1) {
                softmax1024(g_out + (size_t)b * E_DIM + D_OUT + D_IN,
                            g_qphi + (size_t)b * D_IN, lane);
            } else {
                if (lane < 4) {
                    float t = __ldcg(&g_out[(size_t)b * E_DIM + D_OUT + 2 * D_IN + lane]);
                    g_sig[b * 4 + lane] = 1.0f / (1.0f + __expf(-t));
                }
            }
            __threadfence();
            if (lane == 0) atomicAdd(&g_flag[b], 1u);
        }
        return;
    }

    // ---------------- row warps ----------------
    const int gw = bid * 8 + wid;                // 0..1175
    const int e0 = gw;                            // kq iff gw >= D_OUT
    const int e1 = gw + GWN;                      // always kq
    const int e2 = gw + 2 * GWN;                  // valid iff < E_DIM
    const bool v2  = (e2 < E_DIM);
    const bool kq0 = (e0 >= D_OUT);
    const unsigned nkq = (kq0 ? 1u : 0u) + 1u + (v2 ? 1u : 0u);

    float4 A0[8], A1[8], A2[8];
    float4 B0[8], B1[8], B2[8];

    // kq phase: front-batch ALL row loads (up to 24 LDG in flight), then dots.
    auto mv_kq = [&](float4 (&r0)[8], float4 (&r1)[8], float4 (&r2)[8], int b) {
        if (kq0) load_row(w, b, e0, lane, r0);
        load_row(w, b, e1, lane, r1);
        if (v2)  load_row(w, b, e2, lane, r2);
        if (kq0) dot_post(x, y, write_y, b, e0, lane, r0);
        dot_post(x, y, write_y, b, e1, lane, r1);
        if (v2)  dot_post(x, y, write_y, b, e2, lane, r2);
        __threadfence();
        if (lane == 0) atomicAdd(&g_cnt[b], nkq);
    };
    auto mv_y = [&](float4 (&r0)[8], int b) {
        if (!kq0) {
            load_row(w, b, e0, lane, r0);
            dot_post(x, y, write_y, b, e0, lane, r0);
        }
    };
    auto waitflag = [&](int b) {
        while (*(volatile unsigned*)&g_flag[b] < 3u) __nanosleep(64);
        __threadfence();
    };
    auto upd = [&](float4 (&r0)[8], float4 (&r1)[8], float4 (&r2)[8], int b) {
        up_row(wout, b, e0, lane, r0);
        up_row(wout, b, e1, lane, r1);
        if (v2) up_row(wout, b, e2, lane, r2);
    };

    // prologue: batch 0 fully loaded + counted
    mv_kq(A0, A1, A2, 0);
    mv_y(A0, 0);

#pragma unroll 1
    for (int bb = 0; bb < BATCH; bb += 2) {
        // load kq rows of bb+1 (posts count -> softmax(bb+1) runs concurrently)
        mv_kq(B0, B1, B2, bb + 1);
        // update bb from registers (flag wait hidden under the B loads above)
        waitflag(bb);
        upd(A0, A1, A2, bb);
        mv_y(B0, bb + 1);

        if (bb + 2 < BATCH) mv_kq(A0, A1, A2, bb + 2);
        waitflag(bb + 1);
        upd(B0, B1, B2, bb + 1);
        if (bb + 2 < BATCH) mv_y(A0, bb + 2);
    }
}

// ---------------------------------------------------------------------------
// kernel_launch: init + one fused kernel (2 graph nodes).
// ---------------------------------------------------------------------------
extern "C" void kernel_launch(void* const* d_in, const int* in_sizes, int n_in,
                              void* d_out, int out_size)
{
    const float* x = (const float*)d_in[0];
    const float* w = (const float*)d_in[1];
    if (n_in >= 2 && in_sizes[0] != BATCH * D_IN) {
        x = (const float*)d_in[1];
        w = (const float*)d_in[0];
    }

    const size_t wout_elems = (size_t)BATCH * E_DIM * D_IN;
    float* out = (float*)d_out;

    float* y_ptr    = out;
    float* wout_ptr = out + ((size_t)out_size - wout_elems);
    const int write_y = ((size_t)out_size > wout_elems) ? 1 : 0;

    srwm_init<<<1, 1>>>();
    srwm_fused<<<1 + NROWBLK, 256>>>(w, x, y_ptr, wout_ptr, write_y);
}